// round 8
// baseline (speedup 1.0000x reference)
#include <cuda_runtime.h>
#include <cuda_fp16.h>
#include <cstdint>

#define N_USERS 100000
#define N_ITEMS 150000
#define N_NODES (N_USERS + N_ITEMS)
#define N_EDGES 4000000
#define DIM 64

#define SCAN_TB   256
#define SCAN_IPT  4
#define SCAN_TILE (SCAN_TB * SCAN_IPT)                    // 1024
#define N_SCAN_BLOCKS ((N_NODES + SCAN_TILE - 1) / SCAN_TILE)  // 245

// fp16 embeddings: x0 = quantized inputs, x1/x2 = layer outputs (32 MB each)
__device__ __half g_x0[(size_t)N_NODES * DIM];
__device__ __half g_x1[(size_t)N_NODES * DIM];
__device__ __half g_x2[(size_t)N_NODES * DIM];
// CSR machinery (g_cnt zero-initialized at load; scan_add re-zeroes it every
// launch after scan_blocks consumed it -> invariant: cnt==0 at entry)
__device__ int  g_cnt[N_NODES];
__device__ int  g_rp[N_NODES + 1];
__device__ int  g_offs[N_NODES];
__device__ int  g_sums[SCAN_TB];
__device__ int2 g_edges[N_EDGES];          // packed {src, val_bits}, sorted by dst

// ---------- convert fp32 inputs -> fp16 x0 ----------
__global__ void convert_kernel(const float* __restrict__ user_emb,
                               const float* __restrict__ item_emb,
                               __half* __restrict__ x0) {
    size_t i = (size_t)blockIdx.x * blockDim.x + threadIdx.x;  // half2 index
    const size_t total2 = (size_t)N_NODES * DIM / 2;
    if (i >= total2) return;
    const size_t ub2 = (size_t)N_USERS * DIM / 2;
    float2 v;
    if (i < ub2) v = __ldcs(((const float2*)user_emb) + i);
    else         v = __ldcs(((const float2*)item_emb) + (i - ub2));
    ((__half2*)x0)[i] = __float22half2_rn(v);
}

// ---------- histogram: cnt[dst]++ ----------
__global__ void hist_kernel(const int* __restrict__ edst, int* __restrict__ cnt) {
    int i = blockIdx.x * blockDim.x + threadIdx.x;         // edge/4 index
    if (i >= N_EDGES / 4) return;
    int4 d = __ldcs(((const int4*)edst) + i);
    atomicAdd(cnt + d.x, 1);
    atomicAdd(cnt + d.y, 1);
    atomicAdd(cnt + d.z, 1);
    atomicAdd(cnt + d.w, 1);
}

// ---------- exclusive scan, 3 stages ----------
__global__ void scan_blocks(const int* __restrict__ in, int* __restrict__ out,
                            int* __restrict__ sums, int n) {
    __shared__ int wsum[8];
    int tid  = threadIdx.x;
    int base = blockIdx.x * SCAN_TILE + tid * SCAN_IPT;
    int v0 = 0, v1 = 0, v2 = 0, v3 = 0;
    if (base + 3 < n) {
        int4 t = *(const int4*)(in + base);
        v0 = t.x; v1 = t.y; v2 = t.z; v3 = t.w;
    } else {
        if (base     < n) v0 = in[base];
        if (base + 1 < n) v1 = in[base + 1];
        if (base + 2 < n) v2 = in[base + 2];
    }
    int tsum = v0 + v1 + v2 + v3;
    int lane = tid & 31, wid = tid >> 5;
    int inc = tsum;
    #pragma unroll
    for (int o = 1; o < 32; o <<= 1) {
        int t = __shfl_up_sync(0xffffffffu, inc, o);
        if (lane >= o) inc += t;
    }
    if (lane == 31) wsum[wid] = inc;
    __syncthreads();
    if (tid < 8) {
        int w = wsum[tid];
        #pragma unroll
        for (int o = 1; o < 8; o <<= 1) {
            int t = __shfl_up_sync(0xffu, w, o);
            if (tid >= o) w += t;
        }
        wsum[tid] = w;
    }
    __syncthreads();
    int excl = inc - tsum + (wid ? wsum[wid - 1] : 0);
    if (base     < n) out[base]     = excl;
    if (base + 1 < n) out[base + 1] = excl + v0;
    if (base + 2 < n) out[base + 2] = excl + v0 + v1;
    if (base + 3 < n) out[base + 3] = excl + v0 + v1 + v2;
    if (tid == 0) sums[blockIdx.x] = wsum[7];
}

__global__ void scan_sums(int* __restrict__ sums, int nb) {
    __shared__ int wsum[8];
    int tid = threadIdx.x;
    int v = (tid < nb) ? sums[tid] : 0;
    int lane = tid & 31, wid = tid >> 5;
    int inc = v;
    #pragma unroll
    for (int o = 1; o < 32; o <<= 1) {
        int t = __shfl_up_sync(0xffffffffu, inc, o);
        if (lane >= o) inc += t;
    }
    if (lane == 31) wsum[wid] = inc;
    __syncthreads();
    if (tid < 8) {
        int w = wsum[tid];
        #pragma unroll
        for (int o = 1; o < 8; o <<= 1) {
            int t = __shfl_up_sync(0xffu, w, o);
            if (tid >= o) w += t;
        }
        wsum[tid] = w;
    }
    __syncthreads();
    int excl = inc - v + (wid ? wsum[wid - 1] : 0);
    if (tid < nb) sums[tid] = excl;
}

__global__ void scan_add(int* __restrict__ rp, int* __restrict__ offs,
                         const int* __restrict__ sums, int* __restrict__ cnt) {
    int i = blockIdx.x * blockDim.x + threadIdx.x;
    if (i < N_NODES) {
        int v = rp[i] + sums[i >> 10];
        rp[i]   = v;
        offs[i] = v;
        cnt[i]  = 0;                 // reset for next launch (invariant)
    }
    if (i == N_NODES) rp[N_NODES] = N_EDGES;
}

// ---------- scatter edges into dst-sorted packed array ----------
__global__ void scatter_kernel(const int* __restrict__ esrc,
                               const int* __restrict__ edst,
                               const float* __restrict__ ev,
                               int* __restrict__ offs,
                               int2* __restrict__ edges) {
    int i = blockIdx.x * blockDim.x + threadIdx.x;         // edge/4 index
    if (i >= N_EDGES / 4) return;
    int4   s = __ldcs(((const int4*)esrc) + i);
    int4   d = __ldcs(((const int4*)edst) + i);
    float4 w = __ldcs(((const float4*)ev) + i);
    int p0 = atomicAdd(offs + d.x, 1);
    int p1 = atomicAdd(offs + d.y, 1);
    int p2 = atomicAdd(offs + d.z, 1);
    int p3 = atomicAdd(offs + d.w, 1);
    edges[p0] = make_int2(s.x, __float_as_int(w.x));
    edges[p1] = make_int2(s.y, __float_as_int(w.y));
    edges[p2] = make_int2(s.z, __float_as_int(w.z));
    edges[p3] = make_int2(s.w, __float_as_int(w.w));
}

// ---------- gather-only SpMM, high-MLP version ----------
// Warp per node, half2 per lane (128B fp16 row = 1 wavefront per gather).
// Per 32-edge chunk: ONE coalesced edge LDG (lane l reads edge e+l), then
// shuffle-broadcast srcs and issue up to 16 INDEPENDENT gathers back-to-back
// into a register bank before any accumulation -> per-warp MLP 4 -> 16.
template<int FUSE>
__global__ void __launch_bounds__(256) spmm_f16(
    const int2*   __restrict__ edges,
    const int*    __restrict__ rp,
    const __half* __restrict__ x,
    __half*       __restrict__ y,      // !FUSE
    const float*  __restrict__ f_u,    // FUSE: user_emb
    const float*  __restrict__ f_i,    // FUSE: item_emb
    const __half* __restrict__ f_x1,   // FUSE
    const __half* __restrict__ f_x2,   // FUSE
    float*        __restrict__ fout)   // FUSE
{
    int node = (int)((blockIdx.x * blockDim.x + threadIdx.x) >> 5);
    int lane = threadIdx.x & 31;
    if (node >= N_NODES) return;

    int e   = __ldg(rp + node);
    int end = __ldg(rp + node + 1);

    float a0x = 0.f, a0y = 0.f, a1x = 0.f, a1y = 0.f;
    float a2x = 0.f, a2y = 0.f, a3x = 0.f, a3y = 0.f;

    while (e < end) {
        int n = end - e; if (n > 32) n = 32;
        int2 p = make_int2(0, 0);
        if (lane < n) p = __ldg(edges + e + lane);
        int src = p.x, wb = p.y;

        // ---- bank 0: edges [0, min(n,16)) ----
        {
            int n0 = (n < 16) ? n : 16;
            unsigned g[16];
            #pragma unroll
            for (int k = 0; k < 16; ++k) {
                if (k < n0) {
                    int s = __shfl_sync(0xffffffffu, src, k);
                    g[k] = __ldg(((const unsigned*)(x + (size_t)s * DIM)) + lane);
                }
            }
            #pragma unroll
            for (int k = 0; k < 16; ++k) {
                if (k < n0) {
                    float w = __int_as_float(__shfl_sync(0xffffffffu, wb, k));
                    float2 v = __half22float2(*reinterpret_cast<__half2*>(&g[k]));
                    switch (k & 3) {
                        case 0: a0x += w * v.x; a0y += w * v.y; break;
                        case 1: a1x += w * v.x; a1y += w * v.y; break;
                        case 2: a2x += w * v.x; a2y += w * v.y; break;
                        default: a3x += w * v.x; a3y += w * v.y; break;
                    }
                }
            }
        }
        // ---- bank 1: edges [16, n) ----
        if (n > 16) {
            int n1 = n - 16;
            unsigned g[16];
            #pragma unroll
            for (int k = 0; k < 16; ++k) {
                if (k < n1) {
                    int s = __shfl_sync(0xffffffffu, src, k + 16);
                    g[k] = __ldg(((const unsigned*)(x + (size_t)s * DIM)) + lane);
                }
            }
            #pragma unroll
            for (int k = 0; k < 16; ++k) {
                if (k < n1) {
                    float w = __int_as_float(__shfl_sync(0xffffffffu, wb, k + 16));
                    float2 v = __half22float2(*reinterpret_cast<__half2*>(&g[k]));
                    switch (k & 3) {
                        case 0: a0x += w * v.x; a0y += w * v.y; break;
                        case 1: a1x += w * v.x; a1y += w * v.y; break;
                        case 2: a2x += w * v.x; a2y += w * v.y; break;
                        default: a3x += w * v.x; a3y += w * v.y; break;
                    }
                }
            }
        }
        e += n;
    }

    float ox = (a0x + a1x) + (a2x + a3x);
    float oy = (a0y + a1y) + (a2y + a3y);

    const size_t ro = (size_t)node * DIM + (size_t)lane * 2;
    if (FUSE) {
        float2 e0;
        if (node < N_USERS) e0 = __ldcs((const float2*)(f_u + ro));
        else                e0 = __ldcs((const float2*)(f_i + ro - (size_t)N_USERS * DIM));
        float2 q1 = __half22float2(__ldg(((const __half2*)f_x1) + (ro >> 1)));
        float2 q2 = __half22float2(__ldg(((const __half2*)f_x2) + (ro >> 1)));
        float rx = (e0.x + q1.x + q2.x + ox) * 0.25f;
        float ry = (e0.y + q1.y + q2.y + oy) * 0.25f;
        float* p = fout + ro;
        asm volatile("st.global.cs.v2.f32 [%0], {%1, %2};"
                     :: "l"(p), "f"(rx), "f"(ry) : "memory");
    } else {
        __half2 h = __float22half2_rn(make_float2(ox, oy));
        unsigned hu = *reinterpret_cast<unsigned*>(&h);
        __half* p = y + ro;
        asm volatile("st.global.cs.b32 [%0], %1;"
                     :: "l"(p), "r"(hu) : "memory");
    }
}

extern "C" void kernel_launch(void* const* d_in, const int* in_sizes, int n_in,
                              void* d_out, int out_size) {
    const float* user_emb = (const float*)d_in[0];
    const float* item_emb = (const float*)d_in[1];
    const float* evals    = (const float*)d_in[2];
    const int*   esrc     = (const int*)  d_in[3];
    const int*   edst     = (const int*)  d_in[4];
    float* out = (float*)d_out;

    __half *x0, *x1, *x2; int *cnt, *rp, *offs, *sums; int2 *edges;
    cudaGetSymbolAddress((void**)&x0,    g_x0);
    cudaGetSymbolAddress((void**)&x1,    g_x1);
    cudaGetSymbolAddress((void**)&x2,    g_x2);
    cudaGetSymbolAddress((void**)&cnt,   g_cnt);
    cudaGetSymbolAddress((void**)&rp,    g_rp);
    cudaGetSymbolAddress((void**)&offs,  g_offs);
    cudaGetSymbolAddress((void**)&sums,  g_sums);
    cudaGetSymbolAddress((void**)&edges, g_edges);

    const int TB = 256;
    const int g_e4   = (N_EDGES / 4 + TB - 1) / TB;
    const int g_node = (N_NODES + 1 + TB - 1) / TB;
    const int g_cvt  = (int)(((size_t)N_NODES * DIM / 2 + TB - 1) / TB);
    const int g_spmm = (int)(((size_t)N_NODES * 32 + TB - 1) / TB);

    // ---- inputs -> fp16 x0 (independent of CSR build) ----
    convert_kernel<<<g_cvt, TB>>>(user_emb, item_emb, x0);

    // ---- build CSR (counting sort by dst) ----
    hist_kernel<<<g_e4, TB>>>(edst, cnt);
    scan_blocks<<<N_SCAN_BLOCKS, SCAN_TB>>>(cnt, rp, sums, N_NODES);
    scan_sums<<<1, SCAN_TB>>>(sums, N_SCAN_BLOCKS);
    scan_add<<<g_node, TB>>>(rp, offs, sums, cnt);
    scatter_kernel<<<g_e4, TB>>>(esrc, edst, evals, offs, edges);

    // ---- 3 gather-only SpMM layers (layer 3 fused with final combine) ----
    spmm_f16<0><<<g_spmm, TB>>>(edges, rp, x0, x1,
                                nullptr, nullptr, nullptr, nullptr, nullptr);
    spmm_f16<0><<<g_spmm, TB>>>(edges, rp, x1, x2,
                                nullptr, nullptr, nullptr, nullptr, nullptr);
    spmm_f16<1><<<g_spmm, TB>>>(edges, rp, x2, nullptr,
                                user_emb, item_emb, x1, x2, out);
}

// round 9
// speedup vs baseline: 2.1092x; 2.1092x over previous
#include <cuda_runtime.h>
#include <cuda_fp16.h>
#include <cstdint>

#define N_USERS 100000
#define N_ITEMS 150000
#define N_NODES (N_USERS + N_ITEMS)
#define N_EDGES 4000000
#define DIM 64

#define SCAN_TB   256
#define SCAN_IPT  4
#define SCAN_TILE (SCAN_TB * SCAN_IPT)                    // 1024
#define N_SCAN_BLOCKS ((N_NODES + SCAN_TILE - 1) / SCAN_TILE)  // 245

// fp16 embeddings: x0 = quantized inputs, x1/x2 = layer outputs (32 MB each)
__device__ __half g_x0[(size_t)N_NODES * DIM];
__device__ __half g_x1[(size_t)N_NODES * DIM];
__device__ __half g_x2[(size_t)N_NODES * DIM];
// CSR machinery (g_cnt zero-initialized at load; scan_add re-zeroes it every
// launch after scan_blocks consumed it -> invariant: cnt==0 at entry)
__device__ int  g_cnt[N_NODES];
__device__ int  g_rp[N_NODES + 1];
__device__ int  g_offs[N_NODES];
__device__ int  g_sums[SCAN_TB];
__device__ int2 g_edges[N_EDGES];          // packed {src, val_bits}, sorted by dst

// ---------- convert fp32 inputs -> fp16 x0 ----------
__global__ void convert_kernel(const float* __restrict__ user_emb,
                               const float* __restrict__ item_emb,
                               __half* __restrict__ x0) {
    size_t i = (size_t)blockIdx.x * blockDim.x + threadIdx.x;  // half2 index
    const size_t total2 = (size_t)N_NODES * DIM / 2;
    if (i >= total2) return;
    const size_t ub2 = (size_t)N_USERS * DIM / 2;
    float2 v;
    if (i < ub2) v = __ldcs(((const float2*)user_emb) + i);
    else         v = __ldcs(((const float2*)item_emb) + (i - ub2));
    ((__half2*)x0)[i] = __float22half2_rn(v);
}

// ---------- histogram: cnt[dst]++ ----------
__global__ void hist_kernel(const int* __restrict__ edst, int* __restrict__ cnt) {
    int i = blockIdx.x * blockDim.x + threadIdx.x;         // edge/4 index
    if (i >= N_EDGES / 4) return;
    int4 d = __ldcs(((const int4*)edst) + i);
    atomicAdd(cnt + d.x, 1);
    atomicAdd(cnt + d.y, 1);
    atomicAdd(cnt + d.z, 1);
    atomicAdd(cnt + d.w, 1);
}

// ---------- exclusive scan, 3 stages ----------
__global__ void scan_blocks(const int* __restrict__ in, int* __restrict__ out,
                            int* __restrict__ sums, int n) {
    __shared__ int wsum[8];
    int tid  = threadIdx.x;
    int base = blockIdx.x * SCAN_TILE + tid * SCAN_IPT;
    int v0 = 0, v1 = 0, v2 = 0, v3 = 0;
    if (base + 3 < n) {
        int4 t = *(const int4*)(in + base);
        v0 = t.x; v1 = t.y; v2 = t.z; v3 = t.w;
    } else {
        if (base     < n) v0 = in[base];
        if (base + 1 < n) v1 = in[base + 1];
        if (base + 2 < n) v2 = in[base + 2];
    }
    int tsum = v0 + v1 + v2 + v3;
    int lane = tid & 31, wid = tid >> 5;
    int inc = tsum;
    #pragma unroll
    for (int o = 1; o < 32; o <<= 1) {
        int t = __shfl_up_sync(0xffffffffu, inc, o);
        if (lane >= o) inc += t;
    }
    if (lane == 31) wsum[wid] = inc;
    __syncthreads();
    if (tid < 8) {
        int w = wsum[tid];
        #pragma unroll
        for (int o = 1; o < 8; o <<= 1) {
            int t = __shfl_up_sync(0xffu, w, o);
            if (tid >= o) w += t;
        }
        wsum[tid] = w;
    }
    __syncthreads();
    int excl = inc - tsum + (wid ? wsum[wid - 1] : 0);
    if (base     < n) out[base]     = excl;
    if (base + 1 < n) out[base + 1] = excl + v0;
    if (base + 2 < n) out[base + 2] = excl + v0 + v1;
    if (base + 3 < n) out[base + 3] = excl + v0 + v1 + v2;
    if (tid == 0) sums[blockIdx.x] = wsum[7];
}

__global__ void scan_sums(int* __restrict__ sums, int nb) {
    __shared__ int wsum[8];
    int tid = threadIdx.x;
    int v = (tid < nb) ? sums[tid] : 0;
    int lane = tid & 31, wid = tid >> 5;
    int inc = v;
    #pragma unroll
    for (int o = 1; o < 32; o <<= 1) {
        int t = __shfl_up_sync(0xffffffffu, inc, o);
        if (lane >= o) inc += t;
    }
    if (lane == 31) wsum[wid] = inc;
    __syncthreads();
    if (tid < 8) {
        int w = wsum[tid];
        #pragma unroll
        for (int o = 1; o < 8; o <<= 1) {
            int t = __shfl_up_sync(0xffu, w, o);
            if (tid >= o) w += t;
        }
        wsum[tid] = w;
    }
    __syncthreads();
    int excl = inc - v + (wid ? wsum[wid - 1] : 0);
    if (tid < nb) sums[tid] = excl;
}

__global__ void scan_add(int* __restrict__ rp, int* __restrict__ offs,
                         const int* __restrict__ sums, int* __restrict__ cnt) {
    int i = blockIdx.x * blockDim.x + threadIdx.x;
    if (i < N_NODES) {
        int v = rp[i] + sums[i >> 10];
        rp[i]   = v;
        offs[i] = v;
        cnt[i]  = 0;                 // reset for next launch (invariant)
    }
    if (i == N_NODES) rp[N_NODES] = N_EDGES;
}

// ---------- scatter edges into dst-sorted packed array ----------
__global__ void scatter_kernel(const int* __restrict__ esrc,
                               const int* __restrict__ edst,
                               const float* __restrict__ ev,
                               int* __restrict__ offs,
                               int2* __restrict__ edges) {
    int i = blockIdx.x * blockDim.x + threadIdx.x;         // edge/4 index
    if (i >= N_EDGES / 4) return;
    int4   s = __ldcs(((const int4*)esrc) + i);
    int4   d = __ldcs(((const int4*)edst) + i);
    float4 w = __ldcs(((const float4*)ev) + i);
    int p0 = atomicAdd(offs + d.x, 1);
    int p1 = atomicAdd(offs + d.y, 1);
    int p2 = atomicAdd(offs + d.z, 1);
    int p3 = atomicAdd(offs + d.w, 1);
    edges[p0] = make_int2(s.x, __float_as_int(w.x));
    edges[p1] = make_int2(s.y, __float_as_int(w.y));
    edges[p2] = make_int2(s.z, __float_as_int(w.z));
    edges[p3] = make_int2(s.w, __float_as_int(w.w));
}

// ---------- gather-only SpMM: warp per node, half2 per lane ----------
// 8 independent straight-line edge+gather chains (MLP=8, no shuffles).
// fp16 row = 128B = one wavefront per gather; fp32 accumulation.
// FUSE!=0: out = (e0_fp32 + x1 + x2 + acc) * 0.25 written fp32 to d_out.
template<int FUSE>
__global__ void __launch_bounds__(256) spmm_f16(
    const int2*   __restrict__ edges,
    const int*    __restrict__ rp,
    const __half* __restrict__ x,
    __half*       __restrict__ y,      // !FUSE
    const float*  __restrict__ f_u,    // FUSE: user_emb
    const float*  __restrict__ f_i,    // FUSE: item_emb
    const __half* __restrict__ f_x1,   // FUSE
    const __half* __restrict__ f_x2,   // FUSE
    float*        __restrict__ fout)   // FUSE
{
    int node = (int)((blockIdx.x * blockDim.x + threadIdx.x) >> 5);
    int lane = threadIdx.x & 31;
    if (node >= N_NODES) return;

    int e   = __ldg(rp + node);
    int end = __ldg(rp + node + 1);

    float a0x = 0.f, a0y = 0.f, a1x = 0.f, a1y = 0.f;
    float a2x = 0.f, a2y = 0.f, a3x = 0.f, a3y = 0.f;
    float a4x = 0.f, a4y = 0.f, a5x = 0.f, a5y = 0.f;
    float a6x = 0.f, a6y = 0.f, a7x = 0.f, a7y = 0.f;

    // 8-deep independent chains
    for (; e + 7 < end; e += 8) {
        int2 p0 = __ldg(edges + e);
        int2 p1 = __ldg(edges + e + 1);
        int2 p2 = __ldg(edges + e + 2);
        int2 p3 = __ldg(edges + e + 3);
        int2 p4 = __ldg(edges + e + 4);
        int2 p5 = __ldg(edges + e + 5);
        int2 p6 = __ldg(edges + e + 6);
        int2 p7 = __ldg(edges + e + 7);
        float2 v0 = __half22float2(__ldg(((const __half2*)(x + (size_t)p0.x * DIM)) + lane));
        float2 v1 = __half22float2(__ldg(((const __half2*)(x + (size_t)p1.x * DIM)) + lane));
        float2 v2 = __half22float2(__ldg(((const __half2*)(x + (size_t)p2.x * DIM)) + lane));
        float2 v3 = __half22float2(__ldg(((const __half2*)(x + (size_t)p3.x * DIM)) + lane));
        float2 v4 = __half22float2(__ldg(((const __half2*)(x + (size_t)p4.x * DIM)) + lane));
        float2 v5 = __half22float2(__ldg(((const __half2*)(x + (size_t)p5.x * DIM)) + lane));
        float2 v6 = __half22float2(__ldg(((const __half2*)(x + (size_t)p6.x * DIM)) + lane));
        float2 v7 = __half22float2(__ldg(((const __half2*)(x + (size_t)p7.x * DIM)) + lane));
        float w0 = __int_as_float(p0.y);
        float w1 = __int_as_float(p1.y);
        float w2 = __int_as_float(p2.y);
        float w3 = __int_as_float(p3.y);
        float w4 = __int_as_float(p4.y);
        float w5 = __int_as_float(p5.y);
        float w6 = __int_as_float(p6.y);
        float w7 = __int_as_float(p7.y);
        a0x += w0 * v0.x; a0y += w0 * v0.y;
        a1x += w1 * v1.x; a1y += w1 * v1.y;
        a2x += w2 * v2.x; a2y += w2 * v2.y;
        a3x += w3 * v3.x; a3y += w3 * v3.y;
        a4x += w4 * v4.x; a4y += w4 * v4.y;
        a5x += w5 * v5.x; a5y += w5 * v5.y;
        a6x += w6 * v6.x; a6y += w6 * v6.y;
        a7x += w7 * v7.x; a7y += w7 * v7.y;
    }
    // 4-deep tail
    for (; e + 3 < end; e += 4) {
        int2 p0 = __ldg(edges + e);
        int2 p1 = __ldg(edges + e + 1);
        int2 p2 = __ldg(edges + e + 2);
        int2 p3 = __ldg(edges + e + 3);
        float2 v0 = __half22float2(__ldg(((const __half2*)(x + (size_t)p0.x * DIM)) + lane));
        float2 v1 = __half22float2(__ldg(((const __half2*)(x + (size_t)p1.x * DIM)) + lane));
        float2 v2 = __half22float2(__ldg(((const __half2*)(x + (size_t)p2.x * DIM)) + lane));
        float2 v3 = __half22float2(__ldg(((const __half2*)(x + (size_t)p3.x * DIM)) + lane));
        float w0 = __int_as_float(p0.y);
        float w1 = __int_as_float(p1.y);
        float w2 = __int_as_float(p2.y);
        float w3 = __int_as_float(p3.y);
        a0x += w0 * v0.x; a0y += w0 * v0.y;
        a1x += w1 * v1.x; a1y += w1 * v1.y;
        a2x += w2 * v2.x; a2y += w2 * v2.y;
        a3x += w3 * v3.x; a3y += w3 * v3.y;
    }
    for (; e < end; ++e) {
        int2 p = __ldg(edges + e);
        float2 v = __half22float2(__ldg(((const __half2*)(x + (size_t)p.x * DIM)) + lane));
        float w = __int_as_float(p.y);
        a0x += w * v.x; a0y += w * v.y;
    }
    float ox = ((a0x + a1x) + (a2x + a3x)) + ((a4x + a5x) + (a6x + a7x));
    float oy = ((a0y + a1y) + (a2y + a3y)) + ((a4y + a5y) + (a6y + a7y));

    const size_t ro = (size_t)node * DIM + (size_t)lane * 2;
    if (FUSE) {
        float2 e0;
        if (node < N_USERS) e0 = __ldcs((const float2*)(f_u + ro));
        else                e0 = __ldcs((const float2*)(f_i + ro - (size_t)N_USERS * DIM));
        float2 q1 = __half22float2(__ldg(((const __half2*)f_x1) + (ro >> 1)));
        float2 q2 = __half22float2(__ldg(((const __half2*)f_x2) + (ro >> 1)));
        float rx = (e0.x + q1.x + q2.x + ox) * 0.25f;
        float ry = (e0.y + q1.y + q2.y + oy) * 0.25f;
        float* p = fout + ro;
        asm volatile("st.global.cs.v2.f32 [%0], {%1, %2};"
                     :: "l"(p), "f"(rx), "f"(ry) : "memory");
    } else {
        __half2 h = __float22half2_rn(make_float2(ox, oy));
        unsigned hu = *reinterpret_cast<unsigned*>(&h);
        __half* p = y + ro;
        asm volatile("st.global.cs.b32 [%0], %1;"
                     :: "l"(p), "r"(hu) : "memory");
    }
}

extern "C" void kernel_launch(void* const* d_in, const int* in_sizes, int n_in,
                              void* d_out, int out_size) {
    const float* user_emb = (const float*)d_in[0];
    const float* item_emb = (const float*)d_in[1];
    const float* evals    = (const float*)d_in[2];
    const int*   esrc     = (const int*)  d_in[3];
    const int*   edst     = (const int*)  d_in[4];
    float* out = (float*)d_out;

    __half *x0, *x1, *x2; int *cnt, *rp, *offs, *sums; int2 *edges;
    cudaGetSymbolAddress((void**)&x0,    g_x0);
    cudaGetSymbolAddress((void**)&x1,    g_x1);
    cudaGetSymbolAddress((void**)&x2,    g_x2);
    cudaGetSymbolAddress((void**)&cnt,   g_cnt);
    cudaGetSymbolAddress((void**)&rp,    g_rp);
    cudaGetSymbolAddress((void**)&offs,  g_offs);
    cudaGetSymbolAddress((void**)&sums,  g_sums);
    cudaGetSymbolAddress((void**)&edges, g_edges);

    const int TB = 256;
    const int g_e4   = (N_EDGES / 4 + TB - 1) / TB;
    const int g_node = (N_NODES + 1 + TB - 1) / TB;
    const int g_cvt  = (int)(((size_t)N_NODES * DIM / 2 + TB - 1) / TB);
    const int g_spmm = (int)(((size_t)N_NODES * 32 + TB - 1) / TB);

    // ---- inputs -> fp16 x0 (independent of CSR build) ----
    convert_kernel<<<g_cvt, TB>>>(user_emb, item_emb, x0);

    // ---- build CSR (counting sort by dst) ----
    hist_kernel<<<g_e4, TB>>>(edst, cnt);
    scan_blocks<<<N_SCAN_BLOCKS, SCAN_TB>>>(cnt, rp, sums, N_NODES);
    scan_sums<<<1, SCAN_TB>>>(sums, N_SCAN_BLOCKS);
    scan_add<<<g_node, TB>>>(rp, offs, sums, cnt);
    scatter_kernel<<<g_e4, TB>>>(esrc, edst, evals, offs, edges);

    // ---- 3 gather-only SpMM layers (layer 3 fused with final combine) ----
    spmm_f16<0><<<g_spmm, TB>>>(edges, rp, x0, x1,
                                nullptr, nullptr, nullptr, nullptr, nullptr);
    spmm_f16<0><<<g_spmm, TB>>>(edges, rp, x1, x2,
                                nullptr, nullptr, nullptr, nullptr, nullptr);
    spmm_f16<1><<<g_spmm, TB>>>(edges, rp, x2, nullptr,
                                user_emb, item_emb, x1, x2, out);
}

// round 10
// speedup vs baseline: 2.7758x; 1.3160x over previous
#include <cuda_runtime.h>
#include <cuda_fp16.h>
#include <cstdint>

#define N_USERS 100000
#define N_ITEMS 150000
#define N_NODES (N_USERS + N_ITEMS)
#define N_EDGES 4000000
#define DIM 64

#define SCAN_TB   256
#define SCAN_IPT  4
#define SCAN_TILE (SCAN_TB * SCAN_IPT)                    // 1024
#define N_SCAN_BLOCKS ((N_NODES + SCAN_TILE - 1) / SCAN_TILE)  // 245

// fp16 embeddings: x0 = quantized inputs, x1/x2 = layer outputs (32 MB each)
__device__ __half g_x0[(size_t)N_NODES * DIM];
__device__ __half g_x1[(size_t)N_NODES * DIM];
__device__ __half g_x2[(size_t)N_NODES * DIM];
// CSR machinery (g_cnt zero-initialized at load; scan_add re-zeroes it every
// launch after scan_blocks consumed it -> invariant: cnt==0 at entry)
__device__ int  g_cnt[N_NODES];
__device__ int  g_rp[N_NODES + 1];
__device__ int  g_offs[N_NODES];
__device__ int  g_sums[SCAN_TB];
__device__ int2 g_edges[N_EDGES];          // packed {src, val_bits}, sorted by dst

// ---------- convert fp32 inputs -> fp16 x0 ----------
__global__ void convert_kernel(const float* __restrict__ user_emb,
                               const float* __restrict__ item_emb,
                               __half* __restrict__ x0) {
    size_t i = (size_t)blockIdx.x * blockDim.x + threadIdx.x;  // half2 index
    const size_t total2 = (size_t)N_NODES * DIM / 2;
    if (i >= total2) return;
    const size_t ub2 = (size_t)N_USERS * DIM / 2;
    float2 v;
    if (i < ub2) v = __ldcs(((const float2*)user_emb) + i);
    else         v = __ldcs(((const float2*)item_emb) + (i - ub2));
    ((__half2*)x0)[i] = __float22half2_rn(v);
}

// ---------- histogram: cnt[dst]++ ----------
__global__ void hist_kernel(const int* __restrict__ edst, int* __restrict__ cnt) {
    int i = blockIdx.x * blockDim.x + threadIdx.x;         // edge/4 index
    if (i >= N_EDGES / 4) return;
    int4 d = __ldcs(((const int4*)edst) + i);
    atomicAdd(cnt + d.x, 1);
    atomicAdd(cnt + d.y, 1);
    atomicAdd(cnt + d.z, 1);
    atomicAdd(cnt + d.w, 1);
}

// ---------- exclusive scan, 3 stages ----------
__global__ void scan_blocks(const int* __restrict__ in, int* __restrict__ out,
                            int* __restrict__ sums, int n) {
    __shared__ int wsum[8];
    int tid  = threadIdx.x;
    int base = blockIdx.x * SCAN_TILE + tid * SCAN_IPT;
    int v0 = 0, v1 = 0, v2 = 0, v3 = 0;
    if (base + 3 < n) {
        int4 t = *(const int4*)(in + base);
        v0 = t.x; v1 = t.y; v2 = t.z; v3 = t.w;
    } else {
        if (base     < n) v0 = in[base];
        if (base + 1 < n) v1 = in[base + 1];
        if (base + 2 < n) v2 = in[base + 2];
    }
    int tsum = v0 + v1 + v2 + v3;
    int lane = tid & 31, wid = tid >> 5;
    int inc = tsum;
    #pragma unroll
    for (int o = 1; o < 32; o <<= 1) {
        int t = __shfl_up_sync(0xffffffffu, inc, o);
        if (lane >= o) inc += t;
    }
    if (lane == 31) wsum[wid] = inc;
    __syncthreads();
    if (tid < 8) {
        int w = wsum[tid];
        #pragma unroll
        for (int o = 1; o < 8; o <<= 1) {
            int t = __shfl_up_sync(0xffu, w, o);
            if (tid >= o) w += t;
        }
        wsum[tid] = w;
    }
    __syncthreads();
    int excl = inc - tsum + (wid ? wsum[wid - 1] : 0);
    if (base     < n) out[base]     = excl;
    if (base + 1 < n) out[base + 1] = excl + v0;
    if (base + 2 < n) out[base + 2] = excl + v0 + v1;
    if (base + 3 < n) out[base + 3] = excl + v0 + v1 + v2;
    if (tid == 0) sums[blockIdx.x] = wsum[7];
}

__global__ void scan_sums(int* __restrict__ sums, int nb) {
    __shared__ int wsum[8];
    int tid = threadIdx.x;
    int v = (tid < nb) ? sums[tid] : 0;
    int lane = tid & 31, wid = tid >> 5;
    int inc = v;
    #pragma unroll
    for (int o = 1; o < 32; o <<= 1) {
        int t = __shfl_up_sync(0xffffffffu, inc, o);
        if (lane >= o) inc += t;
    }
    if (lane == 31) wsum[wid] = inc;
    __syncthreads();
    if (tid < 8) {
        int w = wsum[tid];
        #pragma unroll
        for (int o = 1; o < 8; o <<= 1) {
            int t = __shfl_up_sync(0xffu, w, o);
            if (tid >= o) w += t;
        }
        wsum[tid] = w;
    }
    __syncthreads();
    int excl = inc - v + (wid ? wsum[wid - 1] : 0);
    if (tid < nb) sums[tid] = excl;
}

__global__ void scan_add(int* __restrict__ rp, int* __restrict__ offs,
                         const int* __restrict__ sums, int* __restrict__ cnt) {
    int i = blockIdx.x * blockDim.x + threadIdx.x;
    if (i < N_NODES) {
        int v = rp[i] + sums[i >> 10];
        rp[i]   = v;
        offs[i] = v;
        cnt[i]  = 0;                 // reset for next launch (invariant)
    }
    if (i == N_NODES) rp[N_NODES] = N_EDGES;
}

// ---------- scatter edges into dst-sorted packed array ----------
__global__ void scatter_kernel(const int* __restrict__ esrc,
                               const int* __restrict__ edst,
                               const float* __restrict__ ev,
                               int* __restrict__ offs,
                               int2* __restrict__ edges) {
    int i = blockIdx.x * blockDim.x + threadIdx.x;         // edge/4 index
    if (i >= N_EDGES / 4) return;
    int4   s = __ldcs(((const int4*)esrc) + i);
    int4   d = __ldcs(((const int4*)edst) + i);
    float4 w = __ldcs(((const float4*)ev) + i);
    int p0 = atomicAdd(offs + d.x, 1);
    int p1 = atomicAdd(offs + d.y, 1);
    int p2 = atomicAdd(offs + d.z, 1);
    int p3 = atomicAdd(offs + d.w, 1);
    edges[p0] = make_int2(s.x, __float_as_int(w.x));
    edges[p1] = make_int2(s.y, __float_as_int(w.y));
    edges[p2] = make_int2(s.z, __float_as_int(w.z));
    edges[p3] = make_int2(s.w, __float_as_int(w.w));
}

// ---------- gather-only SpMM with smem edge staging ----------
// Warp per node, half2 per lane (128B fp16 row = 1 wavefront per gather).
// Per chunk of <=32 edges: ONE coalesced edge LDG into smem, then the k-loop
// reads edges via LDS (29cyc, broadcast) -> gather addresses never wait on a
// pending global load, so gather latencies pipeline across iterations.
template<int FUSE>
__global__ void __launch_bounds__(256) spmm_f16(
    const int2*   __restrict__ edges,
    const int*    __restrict__ rp,
    const __half* __restrict__ x,
    __half*       __restrict__ y,      // !FUSE
    const float*  __restrict__ f_u,    // FUSE: user_emb
    const float*  __restrict__ f_i,    // FUSE: item_emb
    const __half* __restrict__ f_x1,   // FUSE
    const __half* __restrict__ f_x2,   // FUSE
    float*        __restrict__ fout)   // FUSE
{
    __shared__ int2 s_edges[8][32];
    int wib  = threadIdx.x >> 5;       // warp in block
    int node = (int)((blockIdx.x * blockDim.x + threadIdx.x) >> 5);
    int lane = threadIdx.x & 31;
    if (node >= N_NODES) return;

    int e   = __ldg(rp + node);
    int end = __ldg(rp + node + 1);

    float a0x = 0.f, a0y = 0.f, a1x = 0.f, a1y = 0.f;
    float a2x = 0.f, a2y = 0.f, a3x = 0.f, a3y = 0.f;

    while (e < end) {
        int n = end - e; if (n > 32) n = 32;
        if (lane < n) s_edges[wib][lane] = __ldg(edges + e + lane);
        __syncwarp();

        int k = 0;
        for (; k + 3 < n; k += 4) {
            int2 p0 = s_edges[wib][k];
            int2 p1 = s_edges[wib][k + 1];
            int2 p2 = s_edges[wib][k + 2];
            int2 p3 = s_edges[wib][k + 3];
            float2 v0 = __half22float2(__ldg(((const __half2*)(x + (size_t)p0.x * DIM)) + lane));
            float2 v1 = __half22float2(__ldg(((const __half2*)(x + (size_t)p1.x * DIM)) + lane));
            float2 v2 = __half22float2(__ldg(((const __half2*)(x + (size_t)p2.x * DIM)) + lane));
            float2 v3 = __half22float2(__ldg(((const __half2*)(x + (size_t)p3.x * DIM)) + lane));
            float w0 = __int_as_float(p0.y);
            float w1 = __int_as_float(p1.y);
            float w2 = __int_as_float(p2.y);
            float w3 = __int_as_float(p3.y);
            a0x += w0 * v0.x; a0y += w0 * v0.y;
            a1x += w1 * v1.x; a1y += w1 * v1.y;
            a2x += w2 * v2.x; a2y += w2 * v2.y;
            a3x += w3 * v3.x; a3y += w3 * v3.y;
        }
        for (; k < n; ++k) {
            int2 p = s_edges[wib][k];
            float2 v = __half22float2(__ldg(((const __half2*)(x + (size_t)p.x * DIM)) + lane));
            float w = __int_as_float(p.y);
            a0x += w * v.x; a0y += w * v.y;
        }
        __syncwarp();                  // protect smem before next chunk's store
        e += n;
    }

    float ox = (a0x + a1x) + (a2x + a3x);
    float oy = (a0y + a1y) + (a2y + a3y);

    const size_t ro = (size_t)node * DIM + (size_t)lane * 2;
    if (FUSE) {
        float2 e0;
        if (node < N_USERS) e0 = __ldcs((const float2*)(f_u + ro));
        else                e0 = __ldcs((const float2*)(f_i + ro - (size_t)N_USERS * DIM));
        float2 q1 = __half22float2(__ldg(((const __half2*)f_x1) + (ro >> 1)));
        float2 q2 = __half22float2(__ldg(((const __half2*)f_x2) + (ro >> 1)));
        float rx = (e0.x + q1.x + q2.x + ox) * 0.25f;
        float ry = (e0.y + q1.y + q2.y + oy) * 0.25f;
        float* p = fout + ro;
        asm volatile("st.global.cs.v2.f32 [%0], {%1, %2};"
                     :: "l"(p), "f"(rx), "f"(ry) : "memory");
    } else {
        __half2 h = __float22half2_rn(make_float2(ox, oy));
        unsigned hu = *reinterpret_cast<unsigned*>(&h);
        __half* p = y + ro;
        asm volatile("st.global.cs.b32 [%0], %1;"
                     :: "l"(p), "r"(hu) : "memory");
    }
}

extern "C" void kernel_launch(void* const* d_in, const int* in_sizes, int n_in,
                              void* d_out, int out_size) {
    const float* user_emb = (const float*)d_in[0];
    const float* item_emb = (const float*)d_in[1];
    const float* evals    = (const float*)d_in[2];
    const int*   esrc     = (const int*)  d_in[3];
    const int*   edst     = (const int*)  d_in[4];
    float* out = (float*)d_out;

    __half *x0, *x1, *x2; int *cnt, *rp, *offs, *sums; int2 *edges;
    cudaGetSymbolAddress((void**)&x0,    g_x0);
    cudaGetSymbolAddress((void**)&x1,    g_x1);
    cudaGetSymbolAddress((void**)&x2,    g_x2);
    cudaGetSymbolAddress((void**)&cnt,   g_cnt);
    cudaGetSymbolAddress((void**)&rp,    g_rp);
    cudaGetSymbolAddress((void**)&offs,  g_offs);
    cudaGetSymbolAddress((void**)&sums,  g_sums);
    cudaGetSymbolAddress((void**)&edges, g_edges);

    const int TB = 256;
    const int g_e4   = (N_EDGES / 4 + TB - 1) / TB;
    const int g_node = (N_NODES + 1 + TB - 1) / TB;
    const int g_cvt  = (int)(((size_t)N_NODES * DIM / 2 + TB - 1) / TB);
    const int g_spmm = (int)(((size_t)N_NODES * 32 + TB - 1) / TB);

    // ---- inputs -> fp16 x0 (independent of CSR build) ----
    convert_kernel<<<g_cvt, TB>>>(user_emb, item_emb, x0);

    // ---- build CSR (counting sort by dst) ----
    hist_kernel<<<g_e4, TB>>>(edst, cnt);
    scan_blocks<<<N_SCAN_BLOCKS, SCAN_TB>>>(cnt, rp, sums, N_NODES);
    scan_sums<<<1, SCAN_TB>>>(sums, N_SCAN_BLOCKS);
    scan_add<<<g_node, TB>>>(rp, offs, sums, cnt);
    scatter_kernel<<<g_e4, TB>>>(esrc, edst, evals, offs, edges);

    // ---- 3 gather-only SpMM layers (layer 3 fused with final combine) ----
    spmm_f16<0><<<g_spmm, TB>>>(edges, rp, x0, x1,
                                nullptr, nullptr, nullptr, nullptr, nullptr);
    spmm_f16<0><<<g_spmm, TB>>>(edges, rp, x1, x2,
                                nullptr, nullptr, nullptr, nullptr, nullptr);
    spmm_f16<1><<<g_spmm, TB>>>(edges, rp, x2, nullptr,
                                user_emb, item_emb, x1, x2, out);
}